// round 1
// baseline (speedup 1.0000x reference)
#include <cuda_runtime.h>

// N = 2,000,000 rows.
// Inputs (metadata order): rot (N,4) f32, mod (1,) f32, scale (N,2) f32,
//                          p_k (N,3) f32, view_matrix (N,16) f32
// Output: A (N,9) f32
//
// Pure elementwise, HBM-bound: 136 B/row traffic -> ~272 MB total.

__global__ __launch_bounds__(256, 8)
void splat_cov_kernel(const float4* __restrict__ rot,       // (N,4) as float4
                      const float*  __restrict__ mod,       // (1,)
                      const float2* __restrict__ scale,     // (N,2) as float2
                      const float*  __restrict__ p_k,       // (N,3)
                      const float4* __restrict__ vm4,       // (N,16) as 4x float4
                      float*        __restrict__ out,       // (N,9)
                      int n)
{
    int i = blockIdx.x * blockDim.x + threadIdx.x;
    if (i >= n) return;

    const float m = __ldg(mod);

    // rot = (r, x, y, z), unit quaternion
    float4 q = rot[i];
    float r = q.x, x = q.y, y = q.z, z = q.w;

    float R00 = 1.0f - 2.0f * (y * y + z * z);
    float R10 = 2.0f * (x * y + r * z);
    float R20 = 2.0f * (x * z - r * y);
    float R01 = 2.0f * (x * y - r * z);
    float R11 = 1.0f - 2.0f * (x * x + z * z);
    float R21 = 2.0f * (y * z + r * x);

    float2 s = scale[i];
    float s0 = m * s.x;
    float s1 = m * s.y;

    float u0 = s0 * R00, u1 = s0 * R10, u2 = s0 * R20;
    float v0 = s1 * R01, v1 = s1 * R11, v2 = s1 * R21;

    // view_matrix row i: 16 floats = 4 float4s. We need vm[0,1,2], vm[4,5,6],
    // vm[8,9,10], vm[12,13,14].
    float4 c0 = vm4[i * 4 + 0];   // vm[0..3]
    float4 c1 = vm4[i * 4 + 1];   // vm[4..7]
    float4 c2 = vm4[i * 4 + 2];   // vm[8..11]
    float4 c3 = vm4[i * 4 + 3];   // vm[12..15]

    // p_k row i (stride 3 floats, scalar loads)
    const float* p = p_k + (size_t)i * 3;
    float p0 = p[0], p1 = p[1], p2 = p[2];

    float r1s1 = c0.x * u0 + c1.x * u1 + c2.x * u2;
    float r1s2 = c0.x * v0 + c1.x * v1 + c2.x * v2;
    float r2s1 = c0.y * u0 + c1.y * u1 + c2.y * u2;
    float r2s2 = c0.y * v0 + c1.y * v1 + c2.y * v2;
    float r3s1 = c0.z * u0 + c1.z * u1 + c2.z * u2;
    float r3s2 = c0.z * v0 + c1.z * v1 + c2.z * v2;

    float r1p = c0.x * p0 + c1.x * p1 + c2.x * p2 + c3.x;
    float r2p = c0.y * p0 + c1.y * p1 + c2.y * p2 + c3.y;
    float r3p = c0.z * p0 + c1.z * p1 + c2.z * p2 + c3.z;

    // Output row-major (N, 9): [r1s1, r1s2, r1p, r2s1, r2s2, r2p, r3s1, r3s2, r3p]
    float* o = out + (size_t)i * 9;
    o[0] = r1s1;
    o[1] = r1s2;
    o[2] = r1p;
    o[3] = r2s1;
    o[4] = r2s2;
    o[5] = r2p;
    o[6] = r3s1;
    o[7] = r3s2;
    o[8] = r3p;
}

extern "C" void kernel_launch(void* const* d_in, const int* in_sizes, int n_in,
                              void* d_out, int out_size)
{
    const float4* rot   = (const float4*)d_in[0];
    const float*  mod   = (const float*)d_in[1];
    const float2* scale = (const float2*)d_in[2];
    const float*  p_k   = (const float*)d_in[3];
    const float4* vm4   = (const float4*)d_in[4];
    float* out = (float*)d_out;

    int n = in_sizes[0] / 4;   // rot has N*4 elements

    int threads = 256;
    int blocks = (n + threads - 1) / threads;
    splat_cov_kernel<<<blocks, threads>>>(rot, mod, scale, p_k, vm4, out, n);
}

// round 2
// speedup vs baseline: 1.5899x; 1.5899x over previous
#include <cuda_runtime.h>

// N = 2,000,000 rows. Elementwise Gaussian-splat covariance projection.
// Inputs: rot (N,4) f32, mod (1,) f32, scale (N,2) f32, p_k (N,3) f32,
//         view_matrix (N,16) f32.  Output: A (N,9) f32.
//
// All strided accesses (p_k stride-3 loads, out stride-9 stores) are staged
// through shared memory so every global transaction is a coalesced float4.

#define TPB 256

__global__ __launch_bounds__(TPB, 8)
void splat_cov_kernel(const float4* __restrict__ rot,       // (N,4) as float4
                      const float*  __restrict__ mod,       // (1,)
                      const float2* __restrict__ scale,     // (N,2) as float2
                      const float*  __restrict__ p_k,       // (N,3)
                      const float4* __restrict__ vm4,       // (N,16) as 4x float4
                      float*        __restrict__ out,       // (N,9)
                      int n)
{
    __shared__ float s_p[TPB * 3];   // staged p_k rows for this block
    __shared__ float s_o[TPB * 9];   // staged output rows for this block

    const int block_base = blockIdx.x * TPB;
    const int i = block_base + threadIdx.x;
    const int rows = min(TPB, n - block_base);        // rows this block handles

    // ---- Stage p_k cooperatively: fully coalesced float4 loads ----
    {
        const int nfloat = rows * 3;                  // floats to stage
        // block_base*3 = 768*blockIdx -> float4 aligned
        const float4* src = (const float4*)(p_k + (size_t)block_base * 3);
        float4* dst = (float4*)s_p;
        const int nvec = nfloat >> 2;
        for (int t = threadIdx.x; t < nvec; t += TPB) dst[t] = src[t];
        for (int t = (nvec << 2) + threadIdx.x; t < nfloat; t += TPB)
            s_p[t] = p_k[(size_t)block_base * 3 + t];
    }
    __syncthreads();

    if (i < n) {
        const float m = __ldg(mod);

        float4 q = rot[i];                            // (r, x, y, z)
        float r = q.x, x = q.y, y = q.z, z = q.w;

        float R00 = 1.0f - 2.0f * (y * y + z * z);
        float R10 = 2.0f * (x * y + r * z);
        float R20 = 2.0f * (x * z - r * y);
        float R01 = 2.0f * (x * y - r * z);
        float R11 = 1.0f - 2.0f * (x * x + z * z);
        float R21 = 2.0f * (y * z + r * x);

        float2 s = scale[i];
        float s0 = m * s.x;
        float s1 = m * s.y;

        float u0 = s0 * R00, u1 = s0 * R10, u2 = s0 * R20;
        float v0 = s1 * R01, v1 = s1 * R11, v2 = s1 * R21;

        float4 c0 = vm4[(size_t)i * 4 + 0];           // vm[0..3]
        float4 c1 = vm4[(size_t)i * 4 + 1];           // vm[4..7]
        float4 c2 = vm4[(size_t)i * 4 + 2];           // vm[8..11]
        float4 c3 = vm4[(size_t)i * 4 + 3];           // vm[12..15]

        // p_k from smem (stride-3 word reads: odd stride -> conflict-free)
        float p0 = s_p[threadIdx.x * 3 + 0];
        float p1 = s_p[threadIdx.x * 3 + 1];
        float p2 = s_p[threadIdx.x * 3 + 2];

        float r1s1 = c0.x * u0 + c1.x * u1 + c2.x * u2;
        float r1s2 = c0.x * v0 + c1.x * v1 + c2.x * v2;
        float r2s1 = c0.y * u0 + c1.y * u1 + c2.y * u2;
        float r2s2 = c0.y * v0 + c1.y * v1 + c2.y * v2;
        float r3s1 = c0.z * u0 + c1.z * u1 + c2.z * u2;
        float r3s2 = c0.z * v0 + c1.z * v1 + c2.z * v2;

        float r1p = c0.x * p0 + c1.x * p1 + c2.x * p2 + c3.x;
        float r2p = c0.y * p0 + c1.y * p1 + c2.y * p2 + c3.y;
        float r3p = c0.z * p0 + c1.z * p1 + c2.z * p2 + c3.z;

        // stride-9 smem writes: odd stride -> conflict-free
        float* o = s_o + threadIdx.x * 9;
        o[0] = r1s1;
        o[1] = r1s2;
        o[2] = r1p;
        o[3] = r2s1;
        o[4] = r2s2;
        o[5] = r2p;
        o[6] = r3s1;
        o[7] = r3s2;
        o[8] = r3p;
    }
    __syncthreads();

    // ---- Store cooperatively: fully coalesced float4 stores ----
    {
        const int nfloat = rows * 9;
        const size_t out_base = (size_t)block_base * 9;   // 2304*blockIdx -> aligned
        float4* dst = (float4*)(out + out_base);
        const float4* src = (const float4*)s_o;
        const int nvec = nfloat >> 2;
        for (int t = threadIdx.x; t < nvec; t += TPB) dst[t] = src[t];
        for (int t = (nvec << 2) + threadIdx.x; t < nfloat; t += TPB)
            out[out_base + t] = s_o[t];
    }
}

extern "C" void kernel_launch(void* const* d_in, const int* in_sizes, int n_in,
                              void* d_out, int out_size)
{
    const float4* rot   = (const float4*)d_in[0];
    const float*  mod   = (const float*)d_in[1];
    const float2* scale = (const float2*)d_in[2];
    const float*  p_k   = (const float*)d_in[3];
    const float4* vm4   = (const float4*)d_in[4];
    float* out = (float*)d_out;

    int n = in_sizes[0] / 4;   // rot has N*4 elements

    int blocks = (n + TPB - 1) / TPB;
    splat_cov_kernel<<<blocks, TPB>>>(rot, mod, scale, p_k, vm4, out, n);
}

// round 3
// speedup vs baseline: 1.6623x; 1.0455x over previous
#include <cuda_runtime.h>

// N = 2,000,000 rows. Elementwise Gaussian-splat covariance projection.
// Inputs: rot (N,4) f32, mod (1,) f32, scale (N,2) f32, p_k (N,3) f32,
//         view_matrix (N,16) f32.  Output: A (N,9) f32.
//
// R2: 2 rows per thread, front-batched loads for MLP; all strided traffic
// (p_k loads, out stores) staged through smem as coalesced float4.

#define TPB 256
#define RPT 2                       // rows per thread
#define RPB (TPB * RPT)             // rows per block = 512

__global__ __launch_bounds__(TPB, 4)
void splat_cov_kernel(const float4* __restrict__ rot,       // (N,4) as float4
                      const float*  __restrict__ mod,       // (1,)
                      const float2* __restrict__ scale,     // (N,2) as float2
                      const float*  __restrict__ p_k,       // (N,3)
                      const float4* __restrict__ vm4,       // (N,16) as 4x float4
                      float*        __restrict__ out,       // (N,9)
                      int n)
{
    __shared__ float s_p[RPB * 3];   // staged p_k rows (6 KB)
    __shared__ float s_o[RPB * 9];   // staged output rows (18 KB)

    const int block_base = blockIdx.x * RPB;
    const int rows = min(RPB, n - block_base);

    // ---- Stage p_k cooperatively: coalesced float4 loads ----
    {
        const int nfloat = rows * 3;                  // up to 1536 floats
        // block_base*3 = 1536*blockIdx -> float4 aligned
        const float4* src = (const float4*)(p_k + (size_t)block_base * 3);
        float4* dst = (float4*)s_p;
        const int nvec = nfloat >> 2;                 // up to 384
        #pragma unroll 2
        for (int t = threadIdx.x; t < nvec; t += TPB) dst[t] = src[t];
        for (int t = (nvec << 2) + threadIdx.x; t < nfloat; t += TPB)
            s_p[t] = p_k[(size_t)block_base * 3 + t];
    }

    const float m = __ldg(mod);

    // Row indices: thread handles rows (block_base + tid) and (block_base + tid + TPB)
    // -> both sub-batches fully coalesced across the block.
    int idx[RPT];
    bool act[RPT];
    #pragma unroll
    for (int k = 0; k < RPT; k++) {
        idx[k] = block_base + threadIdx.x + k * TPB;
        act[k] = idx[k] < n;
    }

    // ---- Front-batch ALL global loads (maximize MLP) ----
    float4 q[RPT];
    float2 sc[RPT];
    float4 c0[RPT], c1[RPT], c2[RPT], c3[RPT];
    #pragma unroll
    for (int k = 0; k < RPT; k++) {
        if (act[k]) {
            q[k]  = rot[idx[k]];
            sc[k] = scale[idx[k]];
            const float4* v = vm4 + (size_t)idx[k] * 4;
            c0[k] = v[0]; c1[k] = v[1]; c2[k] = v[2]; c3[k] = v[3];
        }
    }

    __syncthreads();   // p_k staged

    #pragma unroll
    for (int k = 0; k < RPT; k++) {
        if (!act[k]) continue;

        float r = q[k].x, x = q[k].y, y = q[k].z, z = q[k].w;

        float R00 = 1.0f - 2.0f * (y * y + z * z);
        float R10 = 2.0f * (x * y + r * z);
        float R20 = 2.0f * (x * z - r * y);
        float R01 = 2.0f * (x * y - r * z);
        float R11 = 1.0f - 2.0f * (x * x + z * z);
        float R21 = 2.0f * (y * z + r * x);

        float s0 = m * sc[k].x;
        float s1 = m * sc[k].y;

        float u0 = s0 * R00, u1 = s0 * R10, u2 = s0 * R20;
        float v0 = s1 * R01, v1 = s1 * R11, v2 = s1 * R21;

        const int lrow = threadIdx.x + k * TPB;       // local row in block
        float p0 = s_p[lrow * 3 + 0];
        float p1 = s_p[lrow * 3 + 1];
        float p2 = s_p[lrow * 3 + 2];

        float r1s1 = c0[k].x * u0 + c1[k].x * u1 + c2[k].x * u2;
        float r1s2 = c0[k].x * v0 + c1[k].x * v1 + c2[k].x * v2;
        float r2s1 = c0[k].y * u0 + c1[k].y * u1 + c2[k].y * u2;
        float r2s2 = c0[k].y * v0 + c1[k].y * v1 + c2[k].y * v2;
        float r3s1 = c0[k].z * u0 + c1[k].z * u1 + c2[k].z * u2;
        float r3s2 = c0[k].z * v0 + c1[k].z * v1 + c2[k].z * v2;

        float r1p = c0[k].x * p0 + c1[k].x * p1 + c2[k].x * p2 + c3[k].x;
        float r2p = c0[k].y * p0 + c1[k].y * p1 + c2[k].y * p2 + c3[k].y;
        float r3p = c0[k].z * p0 + c1[k].z * p1 + c2[k].z * p2 + c3[k].z;

        float* o = s_o + lrow * 9;                    // odd stride: conflict-free
        o[0] = r1s1;
        o[1] = r1s2;
        o[2] = r1p;
        o[3] = r2s1;
        o[4] = r2s2;
        o[5] = r2p;
        o[6] = r3s1;
        o[7] = r3s2;
        o[8] = r3p;
    }

    __syncthreads();   // outputs staged

    // ---- Store cooperatively: coalesced float4 stores ----
    {
        const int nfloat = rows * 9;                  // up to 4608
        const size_t out_base = (size_t)block_base * 9;  // 4608*blockIdx -> aligned
        float4* dst = (float4*)(out + out_base);
        const float4* src = (const float4*)s_o;
        const int nvec = nfloat >> 2;                 // up to 1152
        #pragma unroll 4
        for (int t = threadIdx.x; t < nvec; t += TPB) dst[t] = src[t];
        for (int t = (nvec << 2) + threadIdx.x; t < nfloat; t += TPB)
            out[out_base + t] = s_o[t];
    }
}

extern "C" void kernel_launch(void* const* d_in, const int* in_sizes, int n_in,
                              void* d_out, int out_size)
{
    const float4* rot   = (const float4*)d_in[0];
    const float*  mod   = (const float*)d_in[1];
    const float2* scale = (const float2*)d_in[2];
    const float*  p_k   = (const float*)d_in[3];
    const float4* vm4   = (const float4*)d_in[4];
    float* out = (float*)d_out;

    int n = in_sizes[0] / 4;   // rot has N*4 elements

    int blocks = (n + RPB - 1) / RPB;
    splat_cov_kernel<<<blocks, TPB>>>(rot, mod, scale, p_k, vm4, out, n);
}